// round 9
// baseline (speedup 1.0000x reference)
#include <cuda_runtime.h>
#include <cuda_bf16.h>
#include <math.h>

typedef unsigned int u32;

#define DOF   7
#define NB    5
#define KDIM  256
#define OUTC  42
#define RPB   64
#define BATCH 65536
#define GRID  (BATCH / RPB)   // 1024
#define TPB   256

// ---- smem layout (bytes). A stride 528 (132w%32=4), B stride 272 (68w%32=4):
// both LDSM/STS conflict-free, zero swizzle ALU.
// B stored as two stacked k-halves: rows 0..47 = k[0,128), rows 48..95 = k[128,256).
#define AST    528
#define BST    272
#define A_HI   0                    // 64 x 528 = 33792
#define A_LO   33792                // -> 67584
#define B_HI   67584                // 96 x 272 = 26112 -> 93696
#define B_LO   93696                // -> 119808
#define BIAS_B 119808               // 48 floats
#define SMEM_TOTAL 120064
// aliases after MMA:
#define CS     0                    // 4 x (64*50*4) = 51200 (over A tiles)
#define EB     51200                // 64*77*4 = 19712 -> 70912 (A tail + B_HI head, both dead)

// Pre-converted W tiles in exact stacked padded layout (96 x 136 shorts each)
__device__ __align__(16) unsigned short g_Bhi[96 * 136];
__device__ __align__(16) unsigned short g_Blo[96 * 136];
__device__ __align__(16) float g_bias48[48];

// DMP linear map: y[t] = A[t] . [y0, g, u0..u4, 1]
__constant__ float c_A[11 * 8];

__device__ __forceinline__ u32 sm2u32(const void* p) {
    u32 a; asm("{.reg .u64 t; cvta.to.shared.u64 t,%1; cvt.u32.u64 %0,t;}"
               : "=r"(a) : "l"(p));
    return a;
}
__device__ __forceinline__ void ldsm4(u32 addr, u32& r0, u32& r1, u32& r2, u32& r3) {
    asm volatile("ldmatrix.sync.aligned.m8n8.x4.shared.b16 {%0,%1,%2,%3},[%4];"
                 : "=r"(r0), "=r"(r1), "=r"(r2), "=r"(r3) : "r"(addr));
}
__device__ __forceinline__ void mma16816(float* c, const u32* a, u32 b0, u32 b1) {
    asm volatile(
        "mma.sync.aligned.m16n8k16.row.col.f32.bf16.bf16.f32 "
        "{%0,%1,%2,%3},{%4,%5,%6,%7},{%8,%9},{%0,%1,%2,%3};"
        : "+f"(c[0]), "+f"(c[1]), "+f"(c[2]), "+f"(c[3])
        : "r"(a[0]), "r"(a[1]), "r"(a[2]), "r"(a[3]), "r"(b0), "r"(b1));
}

// ---------------------------------------------------------------------------
// Prep: W -> bf16 hi/lo, stacked padded [n + 48*(k>>7)][k&127] layout + bias.
// ---------------------------------------------------------------------------
__global__ void prep_w_kernel(const float* __restrict__ W,
                              const float* __restrict__ bias)
{
    int gid = blockIdx.x * 256 + threadIdx.x;   // 48*256 = 12288 threads
    int n = gid >> 8, k = gid & 255;
    unsigned short hi = 0, lo = 0;
    if (n < OUTC) {
        float w = __ldg(W + k * OUTC + n);
        u32 uw = __float_as_uint(w);
        float hw = __uint_as_float(uw & 0xFFFF0000u);
        __nv_bfloat16 lb = __float2bfloat16(w - hw);
        hi = (unsigned short)(uw >> 16);
        lo = *(const unsigned short*)&lb;
    }
    int slot = (n + 48 * (k >> 7)) * 136 + (k & 127);
    g_Bhi[slot] = hi;
    g_Blo[slot] = lo;
    // zero the 8 pad shorts of each row (use threads with k in [120,128))
    if ((k & 127) >= 120) {
        int prow = n + 48 * (k >> 7);
        g_Bhi[prow * 136 + 128 + ((k & 127) - 120)] = 0;
        g_Blo[prow * 136 + 128 + ((k & 127) - 120)] = 0;
    }
    if (gid < 48) g_bias48[gid] = (gid < OUTC) ? __ldg(bias + gid) : 0.0f;
}

// ---------------------------------------------------------------------------
__global__ __launch_bounds__(TPB, 2)
void fused_kernel(const float* __restrict__ x, const float* __restrict__ state,
                  float* __restrict__ out)
{
    extern __shared__ __align__(1024) char sm[];
    const u32 smb = sm2u32(sm);
    const int tid = threadIdx.x;
    const int wid = tid >> 5;
    const int lane = tid & 31;
    float* biass = (float*)(sm + BIAS_B);

    // ---- x -> bf16 hi/lo, row-major A[r][k] (stride AST) ----
    const float4* xsrc = (const float4*)(x + (size_t)blockIdx.x * RPB * KDIM);
    #pragma unroll 4
    for (int j = 0; j < (RPB * KDIM / 4) / TPB; j++) {      // 16 iters
        int idx = tid + j * TPB;
        int r = idx >> 6, k4 = idx & 63;
        float4 v = __ldg(xsrc + idx);
        u32 ux = __float_as_uint(v.x), uy = __float_as_uint(v.y);
        u32 uz = __float_as_uint(v.z), uw2 = __float_as_uint(v.w);
        u32 hi01 = __byte_perm(ux, uy, 0x7632);
        u32 hi23 = __byte_perm(uz, uw2, 0x7632);
        float lx = v.x - __uint_as_float(ux & 0xFFFF0000u);
        float ly = v.y - __uint_as_float(uy & 0xFFFF0000u);
        float lz = v.z - __uint_as_float(uz & 0xFFFF0000u);
        float lw2 = v.w - __uint_as_float(uw2 & 0xFFFF0000u);
        u32 lo01, lo23;
        asm("cvt.rn.bf16x2.f32 %0,%1,%2;" : "=r"(lo01) : "f"(ly), "f"(lx));
        asm("cvt.rn.bf16x2.f32 %0,%1,%2;" : "=r"(lo23) : "f"(lw2), "f"(lz));
        u32 off = (u32)(r * AST + k4 * 8);
        *(uint2*)(sm + A_HI + off) = make_uint2(hi01, hi23);
        *(uint2*)(sm + A_LO + off) = make_uint2(lo01, lo23);
    }

    // ---- copy pre-converted W tiles: 96*272/16 = 1632 uint4 per tile ----
    {
        const uint4* sh = (const uint4*)g_Bhi;
        const uint4* sl = (const uint4*)g_Blo;
        uint4* dh = (uint4*)(sm + B_HI);
        uint4* dl = (uint4*)(sm + B_LO);
        #pragma unroll
        for (int j = 0; j < 7; j++) {
            int i = tid + j * TPB;
            if (i < 1632) { dh[i] = __ldg(sh + i); dl[i] = __ldg(sl + i); }
        }
        if (tid < 48) biass[tid] = g_bias48[tid];
    }
    __syncthreads();

    // ---- MMA: 8 warps = 2 m-tiles(32 rows) x 4 k-quarters; 3 passes ----
    const int mw = wid & 1;            // m-tile: rows mw*32..+31
    const int kq = wid >> 1;           // k-quarter: k16 steps kq*4..+3

    float c[2][6][4];
    #pragma unroll
    for (int s2 = 0; s2 < 2; s2++)
        #pragma unroll
        for (int n = 0; n < 6; n++)
            #pragma unroll
            for (int q = 0; q < 4; q++) c[s2][n][q] = 0.0f;

    const u32 arow = (u32)((mw * 32 + (lane & 15)) * AST + (lane >> 4) * 16);
    const u32 brow = (u32)((((lane & 7) | ((lane >> 4) << 3))) * BST
                           + ((lane >> 3) & 1) * 16);
    const u32 aHi = smb + A_HI + arow;
    const u32 aLo = smb + A_LO + arow;
    const u32 bHi = smb + B_HI + brow;
    const u32 bLo = smb + B_LO + brow;

    #pragma unroll
    for (int s = 0; s < 4; s++) {
        int step = kq * 4 + s;                 // k16 step 0..15
        u32 ako = (u32)step * 32u;
        u32 bko = (u32)(step & 7) * 32u + (u32)(step >> 3) * (48u * BST);
        u32 ah[2][4], al[2][4], bh[12], bl[12];
        #pragma unroll
        for (int sub = 0; sub < 2; sub++) {
            u32 ro = (u32)sub * (16u * AST);
            ldsm4(aHi + ro + ako, ah[sub][0], ah[sub][1], ah[sub][2], ah[sub][3]);
            ldsm4(aLo + ro + ako, al[sub][0], al[sub][1], al[sub][2], al[sub][3]);
        }
        #pragma unroll
        for (int nt = 0; nt < 3; nt++) {
            u32 ro = (u32)nt * (16u * BST);
            ldsm4(bHi + ro + bko, bh[nt*4], bh[nt*4+1], bh[nt*4+2], bh[nt*4+3]);
            ldsm4(bLo + ro + bko, bl[nt*4], bl[nt*4+1], bl[nt*4+2], bl[nt*4+3]);
        }
        #pragma unroll
        for (int sub = 0; sub < 2; sub++)
            #pragma unroll
            for (int n = 0; n < 6; n++) {
                int bi = (n >> 1) * 4 + (n & 1) * 2;
                mma16816(c[sub][n], ah[sub], bh[bi], bh[bi + 1]);  // hi*hi
                mma16816(c[sub][n], ah[sub], bl[bi], bl[bi + 1]);  // hi*lo
                mma16816(c[sub][n], al[sub], bh[bi], bh[bi + 1]);  // lo*hi
            }
    }
    __syncthreads();   // tile reads done before aliases are written

    // ---- stage C partials: cs[kq][row][col], row stride 50 floats ----
    {
        float* cs = (float*)(sm + CS) + kq * (RPB * 50);
        int c0 = 2 * (lane & 3);
        #pragma unroll
        for (int sub = 0; sub < 2; sub++) {
            int r0 = mw * 32 + sub * 16 + (lane >> 2);
            #pragma unroll
            for (int n = 0; n < 6; n++) {
                int col = n * 8 + c0;
                *(float2*)&cs[r0 * 50 + col]       = make_float2(c[sub][n][0], c[sub][n][1]);
                *(float2*)&cs[(r0 + 8) * 50 + col] = make_float2(c[sub][n][2], c[sub][n][3]);
            }
        }
    }
    __syncthreads();

    // ---- epilogue: linear DMP map, one thread per batch row ----
    if (tid < RPB) {
        const float* cs = (const float*)(sm + CS) + tid * 50;
        float* eb = (float*)(sm + EB) + tid * 77;
        const float* st = state + ((size_t)(blockIdx.x * RPB + tid)) * DOF;

        float g[DOF], y0v[DOF], ku[DOF], wv[DOF][NB];
        #pragma unroll
        for (int d = 0; d < DOF; d++) {
            y0v[d] = __ldg(st + d);
            g[d] = cs[d] + cs[RPB*50 + d] + cs[2*RPB*50 + d] + cs[3*RPB*50 + d]
                 + biass[d];
            ku[d] = g[d] - y0v[d];
            #pragma unroll
            for (int j = 0; j < NB; j++) {
                int col = DOF + 5 * d + j;
                wv[d][j] = cs[col] + cs[RPB*50 + col] + cs[2*RPB*50 + col]
                         + cs[3*RPB*50 + col] + biass[col];
            }
            eb[d] = y0v[d];                 // t = 0
        }
        #pragma unroll
        for (int t = 1; t <= 10; t++) {
            float a0 = c_A[t*8+0], a1 = c_A[t*8+1], a2 = c_A[t*8+2], a3 = c_A[t*8+3];
            float a4 = c_A[t*8+4], a5 = c_A[t*8+5], a6 = c_A[t*8+6], a7 = c_A[t*8+7];
            #pragma unroll
            for (int d = 0; d < DOF; d++) {
                float v = a2 * wv[d][0];
                v = fmaf(a3, wv[d][1], v);
                v = fmaf(a4, wv[d][2], v);
                v = fmaf(a5, wv[d][3], v);
                v = fmaf(a6, wv[d][4], v);
                float yv = fmaf(a0, y0v[d], a7);
                yv = fmaf(a1, g[d], yv);
                yv = fmaf(v, ku[d], yv);
                eb[t * 7 + d] = yv;
            }
        }
    }
    __syncthreads();

    // ---- coalesced output copy: 64*77 floats = 1232 float4 ----
    const float4* s4 = (const float4*)(sm + EB);
    float4* d4 = (float4*)(out + (size_t)blockIdx.x * RPB * 77);
    #pragma unroll 1
    for (int i = tid; i < (RPB * 77) / 4; i += TPB) d4[i] = s4[i];
}

// ---------------------------------------------------------------------------
// Host: DMP linear map A (8 basis runs of the exact fp32 recursion).
// ---------------------------------------------------------------------------
static float hA[11 * 8];

static void compute_A_host() {
    float c[NB], s2[NB], P[100][NB];
    const float n15 = 11.180339887498949f;     // 5^1.5
    for (int j = 0; j < NB; j++) { c[j] = expf(-0.25f * j); s2[j] = n15 / c[j]; }
    float xv = 1.0f;
    for (int s = 0; s < 100; s++) {
        xv = xv - xv * 0.01f;
        float sum = 0.0f, psi[NB];
        for (int j = 0; j < NB; j++) {
            float d = xv - c[j];
            psi[j] = expf(-0.5f * d * d / s2[j]);
            sum += psi[j];
        }
        for (int j = 0; j < NB; j++) P[s][j] = psi[j] * xv / sum;
    }
    for (int b = 0; b < 8; b++) {              // basis: y0, g, u0..u4, const
        float y = (b == 0) ? 1.0f : 0.0f;
        float gb = (b == 1) ? 1.0f : 0.0f;
        float u[NB];
        for (int j = 0; j < NB; j++) u[j] = (b == 2 + j) ? 1.0f : 0.0f;
        float z = (b == 7) ? 0.05f : 0.0f;
        hA[0 * 8 + b] = y;
        int s = 0;
        for (int tt = 1; tt <= 10; tt++) {
            for (int ss = 0; ss < 10; ss++, s++) {
                float fx = 0.0f;
                for (int j = 0; j < NB; j++) fx += P[s][j] * u[j];
                float dz = 56.25f * (gb - y) - 15.0f * z + fx;
                y = y + z * 0.01f;             // uses old z
                z = z + dz * 0.01f;
            }
            hA[tt * 8 + b] = y;
        }
    }
}

extern "C" void kernel_launch(void* const* d_in, const int* in_sizes, int n_in,
                              void* d_out, int out_size)
{
    const float* x     = (const float*)d_in[0];
    const float* state = (const float*)d_in[1];
    const float* W     = (const float*)d_in[2];
    const float* b     = (const float*)d_in[3];
    float* out = (float*)d_out;

    compute_A_host();
    cudaMemcpyToSymbolAsync(c_A, hA, sizeof(hA), 0, cudaMemcpyHostToDevice);

    prep_w_kernel<<<48, 256>>>(W, b);
    cudaFuncSetAttribute(fused_kernel,
                         cudaFuncAttributeMaxDynamicSharedMemorySize, SMEM_TOTAL);
    fused_kernel<<<GRID, TPB, SMEM_TOTAL>>>(x, state, out);
}

// round 10
// speedup vs baseline: 1.2509x; 1.2509x over previous
#include <cuda_runtime.h>
#include <cuda_bf16.h>
#include <math.h>

typedef unsigned int u32;

#define DOF   7
#define NB    5
#define KDIM  256
#define OUTC  42
#define RPB   64
#define BATCH 65536
#define GRID  (BATCH / RPB)   // 1024
#define TPB   256

// ---- smem layout (bytes). Unpadded 512B rows, XOR-swizzled:
// phys16(r, c) = (c ^ (r & 7)), 16B units; conflict-free for STS and LDSM.
#define A_HI   0                    // 64 x 512 = 32768
#define A_LO   32768                // -> 65536
#define B_HI   65536                // 48 x 512 = 24576 -> 90112
#define B_LO   90112                // -> 114688
#define SMEM_TOTAL 114688           // x2 CTAs = 229376 < SM limit
// aliases after MMA:
#define CS     0                    // 4 x (64*50*4) = 51200 (over A tiles)
#define EB     51200                // 64*77*4 = 19712 -> 70912 (A tail + B_HI, dead)

// Pre-converted, PRE-SWIZZLED W tiles (exact smem byte layout, 48x512B each)
__device__ __align__(16) unsigned short g_Bhi[48 * 256];
__device__ __align__(16) unsigned short g_Blo[48 * 256];
__device__ __align__(16) float g_bias48[48];

// DMP linear map: y[t] = A[t] . [y0, g, u0..u4, 1]
__constant__ float c_A[11 * 8];

__device__ __forceinline__ u32 sm2u32(const void* p) {
    u32 a; asm("{.reg .u64 t; cvta.to.shared.u64 t,%1; cvt.u32.u64 %0,t;}"
               : "=r"(a) : "l"(p));
    return a;
}
__device__ __forceinline__ void ldsm4(u32 addr, u32& r0, u32& r1, u32& r2, u32& r3) {
    asm volatile("ldmatrix.sync.aligned.m8n8.x4.shared.b16 {%0,%1,%2,%3},[%4];"
                 : "=r"(r0), "=r"(r1), "=r"(r2), "=r"(r3) : "r"(addr));
}
__device__ __forceinline__ void mma16816(float* c, const u32* a, u32 b0, u32 b1) {
    asm volatile(
        "mma.sync.aligned.m16n8k16.row.col.f32.bf16.bf16.f32 "
        "{%0,%1,%2,%3},{%4,%5,%6,%7},{%8,%9},{%0,%1,%2,%3};"
        : "+f"(c[0]), "+f"(c[1]), "+f"(c[2]), "+f"(c[3])
        : "r"(a[0]), "r"(a[1]), "r"(a[2]), "r"(a[3]), "r"(b0), "r"(b1));
}

// ---------------------------------------------------------------------------
// Prep (once): W -> bf16 hi/lo, stored pre-swizzled:
//   byte(n, k) = n*512 + ((k>>3) ^ (n&7))*16 + (k&7)*2
// ---------------------------------------------------------------------------
__global__ void prep_w_kernel(const float* __restrict__ W,
                              const float* __restrict__ bias)
{
    int gid = blockIdx.x * 256 + threadIdx.x;   // 48*256 = 12288 threads
    int n = gid >> 8, k = gid & 255;
    unsigned short hi = 0, lo = 0;
    if (n < OUTC) {
        float w = __ldg(W + k * OUTC + n);
        u32 uw = __float_as_uint(w);
        float hw = __uint_as_float(uw & 0xFFFF0000u);
        __nv_bfloat16 lb = __float2bfloat16(w - hw);
        hi = (unsigned short)(uw >> 16);
        lo = *(const unsigned short*)&lb;
    }
    int off = n * 256 + (((k >> 3) ^ (n & 7)) << 3) + (k & 7);   // in shorts
    g_Bhi[off] = hi;
    g_Blo[off] = lo;
    if (gid < 48) g_bias48[gid] = (gid < OUTC) ? __ldg(bias + gid) : 0.0f;
}

// ---------------------------------------------------------------------------
__global__ __launch_bounds__(TPB, 2)
void fused_kernel(const float* __restrict__ x, const float* __restrict__ state,
                  float* __restrict__ out)
{
    extern __shared__ __align__(1024) char sm[];
    const u32 smb = sm2u32(sm);
    const int tid = threadIdx.x;
    const int wid = tid >> 5;
    const int lane = tid & 31;

    // ---- x -> bf16 hi/lo into swizzled A tiles ----
    const float4* xsrc = (const float4*)(x + (size_t)blockIdx.x * RPB * KDIM);
    #pragma unroll 4
    for (int j = 0; j < (RPB * KDIM / 4) / TPB; j++) {      // 16 iters
        int idx = tid + j * TPB;
        int r = idx >> 6, k4 = idx & 63;                     // k4: float4 idx in row
        float4 v = __ldg(xsrc + idx);
        u32 ux = __float_as_uint(v.x), uy = __float_as_uint(v.y);
        u32 uz = __float_as_uint(v.z), uw2 = __float_as_uint(v.w);
        u32 hi01 = __byte_perm(ux, uy, 0x7632);
        u32 hi23 = __byte_perm(uz, uw2, 0x7632);
        float lx = v.x - __uint_as_float(ux & 0xFFFF0000u);
        float ly = v.y - __uint_as_float(uy & 0xFFFF0000u);
        float lz = v.z - __uint_as_float(uz & 0xFFFF0000u);
        float lw2 = v.w - __uint_as_float(uw2 & 0xFFFF0000u);
        u32 lo01, lo23;
        asm("cvt.rn.bf16x2.f32 %0,%1,%2;" : "=r"(lo01) : "f"(ly), "f"(lx));
        asm("cvt.rn.bf16x2.f32 %0,%1,%2;" : "=r"(lo23) : "f"(lw2), "f"(lz));
        // 16B col c = k4>>1; low half selects 8B
        u32 off = (u32)(r * 512) + ((((u32)k4 >> 1) ^ ((u32)r & 7u)) << 4)
                + ((u32)k4 & 1u) * 8u;
        *(uint2*)(sm + A_HI + off) = make_uint2(hi01, hi23);
        *(uint2*)(sm + A_LO + off) = make_uint2(lo01, lo23);
    }

    // ---- copy pre-swizzled W tiles: 24576/16 = 1536 uint4 per tile ----
    {
        const uint4* sh = (const uint4*)g_Bhi;
        const uint4* sl = (const uint4*)g_Blo;
        uint4* dh = (uint4*)(sm + B_HI);
        uint4* dl = (uint4*)(sm + B_LO);
        #pragma unroll
        for (int j = 0; j < 6; j++) {
            int i = tid + j * TPB;
            dh[i] = __ldg(sh + i);
            dl[i] = __ldg(sl + i);
        }
    }
    __syncthreads();

    // ---- MMA: 8 warps = 2 m-tiles(32 rows) x 4 k-quarters; 3 passes ----
    const int mw = wid & 1;            // m-tile: rows mw*32..+31
    const int kq = wid >> 1;           // k-quarter: k16 steps kq*4..+3

    float c[2][6][4];
    #pragma unroll
    for (int s2 = 0; s2 < 2; s2++)
        #pragma unroll
        for (int n = 0; n < 6; n++)
            #pragma unroll
            for (int q = 0; q < 4; q++) c[s2][n][q] = 0.0f;

    const u32 sw  = (u32)(lane & 7);                 // per-thread swizzle constant
    const u32 arow = (u32)((mw * 32 + (lane & 15)) * 512);
    const u32 acolL = (u32)(lane >> 4);              // 0/1: +8 k within step
    const u32 brow = (u32)((((lane & 7) | ((lane >> 4) << 3))) * 512);
    const u32 bcolL = (u32)((lane >> 3) & 1);

    #pragma unroll
    for (int s = 0; s < 4; s++) {
        u32 step = (u32)(kq * 4 + s);                // k16 step 0..15
        u32 ac = ((step * 2u + acolL) ^ sw) << 4;    // A 16B col, swizzled
        u32 bc = ((step * 2u + bcolL) ^ sw) << 4;    // B 16B col, swizzled
        u32 ah[2][4], al[2][4], bh[12], bl[12];
        #pragma unroll
        for (int sub = 0; sub < 2; sub++) {
            u32 ad = arow + (u32)sub * (16u * 512u) + ac;
            ldsm4(smb + A_HI + ad, ah[sub][0], ah[sub][1], ah[sub][2], ah[sub][3]);
            ldsm4(smb + A_LO + ad, al[sub][0], al[sub][1], al[sub][2], al[sub][3]);
        }
        #pragma unroll
        for (int nt = 0; nt < 3; nt++) {
            u32 bd = brow + (u32)nt * (16u * 512u) + bc;
            ldsm4(smb + B_HI + bd, bh[nt*4], bh[nt*4+1], bh[nt*4+2], bh[nt*4+3]);
            ldsm4(smb + B_LO + bd, bl[nt*4], bl[nt*4+1], bl[nt*4+2], bl[nt*4+3]);
        }
        #pragma unroll
        for (int sub = 0; sub < 2; sub++)
            #pragma unroll
            for (int n = 0; n < 6; n++) {
                int bi = (n >> 1) * 4 + (n & 1) * 2;
                mma16816(c[sub][n], ah[sub], bh[bi], bh[bi + 1]);  // hi*hi
                mma16816(c[sub][n], ah[sub], bl[bi], bl[bi + 1]);  // hi*lo
                mma16816(c[sub][n], al[sub], bh[bi], bh[bi + 1]);  // lo*hi
            }
    }
    __syncthreads();   // tile reads done before aliases are written

    // ---- stage C partials: cs[kq][row][col], row stride 50 floats ----
    {
        float* cs = (float*)(sm + CS) + kq * (RPB * 50);
        int c0 = 2 * (lane & 3);
        #pragma unroll
        for (int sub = 0; sub < 2; sub++) {
            int r0 = mw * 32 + sub * 16 + (lane >> 2);
            #pragma unroll
            for (int n = 0; n < 6; n++) {
                int col = n * 8 + c0;
                *(float2*)&cs[r0 * 50 + col]       = make_float2(c[sub][n][0], c[sub][n][1]);
                *(float2*)&cs[(r0 + 8) * 50 + col] = make_float2(c[sub][n][2], c[sub][n][3]);
            }
        }
    }
    __syncthreads();

    // ---- epilogue: linear DMP map, 2 threads per row (t-split) ----
    if (tid < 2 * RPB) {
        const int row  = tid & 63;
        const int half = tid >> 6;                   // 0: t 0..5, 1: t 6..10
        const float* cs = (const float*)(sm + CS) + row * 50;
        float* eb = (float*)(sm + EB) + row * 77;
        const float* st = state + ((size_t)(blockIdx.x * RPB + row)) * DOF;

        float g[DOF], y0v[DOF], ku[DOF], wv[DOF][NB];
        #pragma unroll
        for (int d = 0; d < DOF; d++) {
            y0v[d] = __ldg(st + d);
            g[d] = cs[d] + cs[RPB*50 + d] + cs[2*RPB*50 + d] + cs[3*RPB*50 + d]
                 + __ldg(g_bias48 + d);
            ku[d] = g[d] - y0v[d];
            #pragma unroll
            for (int j = 0; j < NB; j++) {
                int col = DOF + 5 * d + j;
                wv[d][j] = cs[col] + cs[RPB*50 + col] + cs[2*RPB*50 + col]
                         + cs[3*RPB*50 + col] + __ldg(g_bias48 + col);
            }
            if (half == 0) eb[d] = y0v[d];           // t = 0
        }
        int t0 = half ? 6 : 1, t1 = half ? 10 : 5;
        for (int t = t0; t <= t1; t++) {
            float a0 = c_A[t*8+0], a1 = c_A[t*8+1], a2 = c_A[t*8+2], a3 = c_A[t*8+3];
            float a4 = c_A[t*8+4], a5 = c_A[t*8+5], a6 = c_A[t*8+6], a7 = c_A[t*8+7];
            #pragma unroll
            for (int d = 0; d < DOF; d++) {
                float v = a2 * wv[d][0];
                v = fmaf(a3, wv[d][1], v);
                v = fmaf(a4, wv[d][2], v);
                v = fmaf(a5, wv[d][3], v);
                v = fmaf(a6, wv[d][4], v);
                float yv = fmaf(a0, y0v[d], a7);
                yv = fmaf(a1, g[d], yv);
                yv = fmaf(v, ku[d], yv);
                eb[t * 7 + d] = yv;
            }
        }
    }
    __syncthreads();

    // ---- coalesced output copy: 64*77 floats = 1232 float4 ----
    const float4* s4 = (const float4*)(sm + EB);
    float4* d4 = (float4*)(out + (size_t)blockIdx.x * RPB * 77);
    #pragma unroll
    for (int j = 0; j < 5; j++) {
        int i = tid + j * TPB;
        if (i < (RPB * 77) / 4) d4[i] = s4[i];
    }
}

// ---------------------------------------------------------------------------
// Host: DMP linear map A (8 basis runs of the exact fp32 recursion).
// ---------------------------------------------------------------------------
static float hA[11 * 8];

static void compute_A_host() {
    float c[NB], s2[NB], P[100][NB];
    const float n15 = 11.180339887498949f;     // 5^1.5
    for (int j = 0; j < NB; j++) { c[j] = expf(-0.25f * j); s2[j] = n15 / c[j]; }
    float xv = 1.0f;
    for (int s = 0; s < 100; s++) {
        xv = xv - xv * 0.01f;
        float sum = 0.0f, psi[NB];
        for (int j = 0; j < NB; j++) {
            float d = xv - c[j];
            psi[j] = expf(-0.5f * d * d / s2[j]);
            sum += psi[j];
        }
        for (int j = 0; j < NB; j++) P[s][j] = psi[j] * xv / sum;
    }
    for (int b = 0; b < 8; b++) {              // basis: y0, g, u0..u4, const
        float y = (b == 0) ? 1.0f : 0.0f;
        float gb = (b == 1) ? 1.0f : 0.0f;
        float u[NB];
        for (int j = 0; j < NB; j++) u[j] = (b == 2 + j) ? 1.0f : 0.0f;
        float z = (b == 7) ? 0.05f : 0.0f;
        hA[0 * 8 + b] = y;
        int s = 0;
        for (int tt = 1; tt <= 10; tt++) {
            for (int ss = 0; ss < 10; ss++, s++) {
                float fx = 0.0f;
                for (int j = 0; j < NB; j++) fx += P[s][j] * u[j];
                float dz = 56.25f * (gb - y) - 15.0f * z + fx;
                y = y + z * 0.01f;             // uses old z
                z = z + dz * 0.01f;
            }
            hA[tt * 8 + b] = y;
        }
    }
}

extern "C" void kernel_launch(void* const* d_in, const int* in_sizes, int n_in,
                              void* d_out, int out_size)
{
    const float* x     = (const float*)d_in[0];
    const float* state = (const float*)d_in[1];
    const float* W     = (const float*)d_in[2];
    const float* b     = (const float*)d_in[3];
    float* out = (float*)d_out;

    compute_A_host();
    cudaMemcpyToSymbolAsync(c_A, hA, sizeof(hA), 0, cudaMemcpyHostToDevice);

    prep_w_kernel<<<48, 256>>>(W, b);
    cudaFuncSetAttribute(fused_kernel,
                         cudaFuncAttributeMaxDynamicSharedMemorySize, SMEM_TOTAL);
    fused_kernel<<<GRID, TPB, SMEM_TOTAL>>>(x, state, out);
}

// round 11
// speedup vs baseline: 1.4059x; 1.1239x over previous
#include <cuda_runtime.h>
#include <cuda_fp16.h>
#include <math.h>

typedef unsigned int u32;

#define DOF   7
#define NB    5
#define KDIM  256
#define OUTC  42
#define RPB   64
#define BATCH 65536
#define GRID  (BATCH / RPB)   // 1024
#define TPB   256

// ---- smem layout (bytes). Unpadded 512B rows, XOR-swizzled:
// phys16(r, c) = (c ^ (r & 7)), 16B units; conflict-free for STS/LDSM/cp.async.
#define A_HI   0                    // 64 x 512 = 32768 (x in fp16, single tile)
#define B_HI   32768                // 48 x 512 = 24576 -> 57344
#define B_LO   57344                // -> 81920
#define SMEM_TOTAL 81920            // x2 CTAs = 163840, regs 2x256x128 = full RF
// aliases after MMA:
#define CS     0                    // 4 x (64*50*4) = 51200
#define EB     51200                // 64*77*4 = 19712 -> 70912 < 81920

// Pre-converted, PRE-SWIZZLED W tiles (exact smem byte layout, 48x512B each)
__device__ __align__(16) unsigned short g_Bhi[48 * 256];
__device__ __align__(16) unsigned short g_Blo[48 * 256];
__device__ __align__(16) float g_bias48[48];

// DMP linear map: y[t] = A[t] . [y0, g, u0..u4, 1]
__constant__ float c_A[11 * 8];

__device__ __forceinline__ u32 sm2u32(const void* p) {
    u32 a; asm("{.reg .u64 t; cvta.to.shared.u64 t,%1; cvt.u32.u64 %0,t;}"
               : "=r"(a) : "l"(p));
    return a;
}
__device__ __forceinline__ void ldsm4(u32 addr, u32& r0, u32& r1, u32& r2, u32& r3) {
    asm volatile("ldmatrix.sync.aligned.m8n8.x4.shared.b16 {%0,%1,%2,%3},[%4];"
                 : "=r"(r0), "=r"(r1), "=r"(r2), "=r"(r3) : "r"(addr));
}
__device__ __forceinline__ void mma16816(float* c, const u32* a, u32 b0, u32 b1) {
    asm volatile(
        "mma.sync.aligned.m16n8k16.row.col.f32.f16.f16.f32 "
        "{%0,%1,%2,%3},{%4,%5,%6,%7},{%8,%9},{%0,%1,%2,%3};"
        : "+f"(c[0]), "+f"(c[1]), "+f"(c[2]), "+f"(c[3])
        : "r"(a[0]), "r"(a[1]), "r"(a[2]), "r"(a[3]), "r"(b0), "r"(b1));
}
__device__ __forceinline__ void cp_async16(u32 dst, const void* src) {
    asm volatile("cp.async.cg.shared.global [%0],[%1],16;" :: "r"(dst), "l"(src));
}

// ---------------------------------------------------------------------------
// Prep (once): W -> fp16 hi/lo, stored pre-swizzled:
//   short-off(n, k) = n*256 + (((k>>3) ^ (n&7)) << 3) + (k&7)
// ---------------------------------------------------------------------------
__global__ void prep_w_kernel(const float* __restrict__ W,
                              const float* __restrict__ bias)
{
    int gid = blockIdx.x * 256 + threadIdx.x;   // 48*256 = 12288 threads
    int n = gid >> 8, k = gid & 255;
    unsigned short hi = 0, lo = 0;
    if (n < OUTC) {
        float w = __ldg(W + k * OUTC + n);
        __half h = __float2half_rn(w);
        __half l = __float2half_rn(w - __half2float(h));
        hi = *(const unsigned short*)&h;
        lo = *(const unsigned short*)&l;
    }
    int off = n * 256 + (((k >> 3) ^ (n & 7)) << 3) + (k & 7);
    g_Bhi[off] = hi;
    g_Blo[off] = lo;
    if (gid < 48) g_bias48[gid] = (gid < OUTC) ? __ldg(bias + gid) : 0.0f;
}

// ---------------------------------------------------------------------------
__global__ __launch_bounds__(TPB, 2)
void fused_kernel(const float* __restrict__ x, const float* __restrict__ state,
                  float* __restrict__ out)
{
    extern __shared__ __align__(1024) char sm[];
    const u32 smb = sm2u32(sm);
    const int tid = threadIdx.x;
    const int wid = tid >> 5;
    const int lane = tid & 31;

    // ---- B tiles via cp.async (pre-swizzled layout: straight 16B copy) ----
    {
        const uint4* sh = (const uint4*)g_Bhi;   // 1536 uint4 each
        const uint4* sl = (const uint4*)g_Blo;
        #pragma unroll
        for (int j = 0; j < 6; j++) {
            int i = tid + j * TPB;
            cp_async16(smb + B_HI + 16 * i, sh + i);
            cp_async16(smb + B_LO + 16 * i, sl + i);
        }
        asm volatile("cp.async.commit_group;");
    }

    // ---- x -> fp16 (single pass) into swizzled A tile ----
    const float4* xsrc = (const float4*)(x + (size_t)blockIdx.x * RPB * KDIM);
    #pragma unroll 4
    for (int j = 0; j < (RPB * KDIM / 4) / TPB; j++) {      // 16 iters
        int idx = tid + j * TPB;
        int r = idx >> 6, k4 = idx & 63;                     // k4: float4 idx in row
        float4 v = __ldg(xsrc + idx);
        __half2 h01 = __floats2half2_rn(v.x, v.y);           // .x = low half
        __half2 h23 = __floats2half2_rn(v.z, v.w);
        u32 off = (u32)(r * 512) + ((((u32)k4 >> 1) ^ ((u32)r & 7u)) << 4)
                + ((u32)k4 & 1u) * 8u;
        *(uint2*)(sm + A_HI + off) =
            make_uint2(*(const u32*)&h01, *(const u32*)&h23);
    }
    asm volatile("cp.async.wait_group 0;");
    __syncthreads();

    // ---- MMA: 8 warps = 2 m-tiles(32 rows) x 4 k-quarters; 2 passes ----
    const int mw = wid & 1;            // m-tile: rows mw*32..+31
    const int kq = wid >> 1;           // k-quarter: k16 steps kq*4..+3

    float c[2][6][4];
    #pragma unroll
    for (int s2 = 0; s2 < 2; s2++)
        #pragma unroll
        for (int n = 0; n < 6; n++)
            #pragma unroll
            for (int q = 0; q < 4; q++) c[s2][n][q] = 0.0f;

    const u32 sw  = (u32)(lane & 7);                 // per-thread swizzle constant
    const u32 arow = (u32)((mw * 32 + (lane & 15)) * 512);
    const u32 acolL = (u32)(lane >> 4);              // 0/1: +8 k within step
    const u32 brow = (u32)((((lane & 7) | ((lane >> 4) << 3))) * 512);
    const u32 bcolL = (u32)((lane >> 3) & 1);

    #pragma unroll
    for (int s = 0; s < 4; s++) {
        u32 step = (u32)(kq * 4 + s);                // k16 step 0..15
        u32 ac = ((step * 2u + acolL) ^ sw) << 4;    // A 16B col, swizzled
        u32 bc = ((step * 2u + bcolL) ^ sw) << 4;    // B 16B col, swizzled
        u32 ah[2][4], bh[12], bl[12];
        #pragma unroll
        for (int sub = 0; sub < 2; sub++) {
            u32 ad = arow + (u32)sub * (16u * 512u) + ac;
            ldsm4(smb + A_HI + ad, ah[sub][0], ah[sub][1], ah[sub][2], ah[sub][3]);
        }
        #pragma unroll
        for (int nt = 0; nt < 3; nt++) {
            u32 bd = brow + (u32)nt * (16u * 512u) + bc;
            ldsm4(smb + B_HI + bd, bh[nt*4], bh[nt*4+1], bh[nt*4+2], bh[nt*4+3]);
            ldsm4(smb + B_LO + bd, bl[nt*4], bl[nt*4+1], bl[nt*4+2], bl[nt*4+3]);
        }
        #pragma unroll
        for (int sub = 0; sub < 2; sub++)
            #pragma unroll
            for (int n = 0; n < 6; n++) {
                int bi = (n >> 1) * 4 + (n & 1) * 2;
                mma16816(c[sub][n], ah[sub], bh[bi], bh[bi + 1]);  // x*W_hi
                mma16816(c[sub][n], ah[sub], bl[bi], bl[bi + 1]);  // x*W_lo
            }
    }
    __syncthreads();   // tile reads done before aliases are written

    // ---- stage C partials: cs[kq][row][col], row stride 50 floats ----
    {
        float* cs = (float*)(sm + CS) + kq * (RPB * 50);
        int c0 = 2 * (lane & 3);
        #pragma unroll
        for (int sub = 0; sub < 2; sub++) {
            int r0 = mw * 32 + sub * 16 + (lane >> 2);
            #pragma unroll
            for (int n = 0; n < 6; n++) {
                int col = n * 8 + c0;
                *(float2*)&cs[r0 * 50 + col]       = make_float2(c[sub][n][0], c[sub][n][1]);
                *(float2*)&cs[(r0 + 8) * 50 + col] = make_float2(c[sub][n][2], c[sub][n][3]);
            }
        }
    }
    __syncthreads();

    // ---- epilogue: linear DMP map, 2 threads per row (t-split) ----
    if (tid < 2 * RPB) {
        const int row  = tid & 63;
        const int half = tid >> 6;                   // 0: t 0..5, 1: t 6..10
        const float* cs = (const float*)(sm + CS) + row * 50;
        float* eb = (float*)(sm + EB) + row * 77;
        const float* st = state + ((size_t)(blockIdx.x * RPB + row)) * DOF;

        float g[DOF], y0v[DOF], ku[DOF], wv[DOF][NB];
        #pragma unroll
        for (int d = 0; d < DOF; d++) {
            y0v[d] = __ldg(st + d);
            g[d] = cs[d] + cs[RPB*50 + d] + cs[2*RPB*50 + d] + cs[3*RPB*50 + d]
                 + __ldg(g_bias48 + d);
            ku[d] = g[d] - y0v[d];
            #pragma unroll
            for (int j = 0; j < NB; j++) {
                int col = DOF + 5 * d + j;
                wv[d][j] = cs[col] + cs[RPB*50 + col] + cs[2*RPB*50 + col]
                         + cs[3*RPB*50 + col] + __ldg(g_bias48 + col);
            }
            if (half == 0) eb[d] = y0v[d];           // t = 0
        }
        int t0 = half ? 6 : 1, t1 = half ? 10 : 5;
        for (int t = t0; t <= t1; t++) {
            float a0 = c_A[t*8+0], a1 = c_A[t*8+1], a2 = c_A[t*8+2], a3 = c_A[t*8+3];
            float a4 = c_A[t*8+4], a5 = c_A[t*8+5], a6 = c_A[t*8+6], a7 = c_A[t*8+7];
            #pragma unroll
            for (int d = 0; d < DOF; d++) {
                float v = a2 * wv[d][0];
                v = fmaf(a3, wv[d][1], v);
                v = fmaf(a4, wv[d][2], v);
                v = fmaf(a5, wv[d][3], v);
                v = fmaf(a6, wv[d][4], v);
                float yv = fmaf(a0, y0v[d], a7);
                yv = fmaf(a1, g[d], yv);
                yv = fmaf(v, ku[d], yv);
                eb[t * 7 + d] = yv;
            }
        }
    }
    __syncthreads();

    // ---- coalesced output copy: 64*77 floats = 1232 float4 ----
    const float4* s4 = (const float4*)(sm + EB);
    float4* d4 = (float4*)(out + (size_t)blockIdx.x * RPB * 77);
    #pragma unroll
    for (int j = 0; j < 5; j++) {
        int i = tid + j * TPB;
        if (i < (RPB * 77) / 4) d4[i] = s4[i];
    }
}

// ---------------------------------------------------------------------------
// Host: DMP linear map A (8 basis runs of the exact fp32 recursion).
// ---------------------------------------------------------------------------
static float hA[11 * 8];

static void compute_A_host() {
    float c[NB], s2[NB], P[100][NB];
    const float n15 = 11.180339887498949f;     // 5^1.5
    for (int j = 0; j < NB; j++) { c[j] = expf(-0.25f * j); s2[j] = n15 / c[j]; }
    float xv = 1.0f;
    for (int s = 0; s < 100; s++) {
        xv = xv - xv * 0.01f;
        float sum = 0.0f, psi[NB];
        for (int j = 0; j < NB; j++) {
            float d = xv - c[j];
            psi[j] = expf(-0.5f * d * d / s2[j]);
            sum += psi[j];
        }
        for (int j = 0; j < NB; j++) P[s][j] = psi[j] * xv / sum;
    }
    for (int b = 0; b < 8; b++) {              // basis: y0, g, u0..u4, const
        float y = (b == 0) ? 1.0f : 0.0f;
        float gb = (b == 1) ? 1.0f : 0.0f;
        float u[NB];
        for (int j = 0; j < NB; j++) u[j] = (b == 2 + j) ? 1.0f : 0.0f;
        float z = (b == 7) ? 0.05f : 0.0f;
        hA[0 * 8 + b] = y;
        int s = 0;
        for (int tt = 1; tt <= 10; tt++) {
            for (int ss = 0; ss < 10; ss++, s++) {
                float fx = 0.0f;
                for (int j = 0; j < NB; j++) fx += P[s][j] * u[j];
                float dz = 56.25f * (gb - y) - 15.0f * z + fx;
                y = y + z * 0.01f;             // uses old z
                z = z + dz * 0.01f;
            }
            hA[tt * 8 + b] = y;
        }
    }
}

extern "C" void kernel_launch(void* const* d_in, const int* in_sizes, int n_in,
                              void* d_out, int out_size)
{
    const float* x     = (const float*)d_in[0];
    const float* state = (const float*)d_in[1];
    const float* W     = (const float*)d_in[2];
    const float* b     = (const float*)d_in[3];
    float* out = (float*)d_out;

    compute_A_host();
    cudaMemcpyToSymbolAsync(c_A, hA, sizeof(hA), 0, cudaMemcpyHostToDevice);

    prep_w_kernel<<<48, 256>>>(W, b);
    cudaFuncSetAttribute(fused_kernel,
                         cudaFuncAttributeMaxDynamicSharedMemorySize, SMEM_TOTAL);
    fused_kernel<<<GRID, TPB, SMEM_TOTAL>>>(x, state, out);
}

// round 12
// speedup vs baseline: 1.7320x; 1.2320x over previous
#include <cuda_runtime.h>
#include <cuda_fp16.h>
#include <math.h>

typedef unsigned int u32;

#define DOF   7
#define NB    5
#define KDIM  256
#define OUTC  42
#define RPB   128
#define BATCH 65536
#define GRID  (BATCH / RPB)   // 512
#define TPB   256

// ---- smem layout (bytes). Unpadded 512B rows, XOR-swizzled:
// phys16(r, c) = (c ^ (r & 7)), 16B units; conflict-free for STS/LDSM/cp.async.
#define A_HI   0                    // 128 x 512 = 65536 (x in fp16)
#define B_HI   65536                // 48 x 512 = 24576 -> 90112 (W in fp16, single)
#define SMEM_TOTAL 90624            // x2 CTAs = 181248 < SM limit
// aliases after MMA:
#define CS     0                    // 2 x (128*50*4) = 51200 (over A tile)
#define EB     51200                // 128*77*4 = 39424 -> 90624

// Pre-converted, PRE-SWIZZLED W tile (exact smem byte layout, 48x512B)
__device__ __align__(16) unsigned short g_Bhi[48 * 256];
__device__ __align__(16) float g_bias48[48];

// DMP linear map: y[t] = A[t] . [y0, g, u0..u4, 1]
__constant__ float c_A[11 * 8];

__device__ __forceinline__ u32 sm2u32(const void* p) {
    u32 a; asm("{.reg .u64 t; cvta.to.shared.u64 t,%1; cvt.u32.u64 %0,t;}"
               : "=r"(a) : "l"(p));
    return a;
}
__device__ __forceinline__ void ldsm4(u32 addr, u32& r0, u32& r1, u32& r2, u32& r3) {
    asm volatile("ldmatrix.sync.aligned.m8n8.x4.shared.b16 {%0,%1,%2,%3},[%4];"
                 : "=r"(r0), "=r"(r1), "=r"(r2), "=r"(r3) : "r"(addr));
}
__device__ __forceinline__ void mma16816(float* c, const u32* a, u32 b0, u32 b1) {
    asm volatile(
        "mma.sync.aligned.m16n8k16.row.col.f32.f16.f16.f32 "
        "{%0,%1,%2,%3},{%4,%5,%6,%7},{%8,%9},{%0,%1,%2,%3};"
        : "+f"(c[0]), "+f"(c[1]), "+f"(c[2]), "+f"(c[3])
        : "r"(a[0]), "r"(a[1]), "r"(a[2]), "r"(a[3]), "r"(b0), "r"(b1));
}
__device__ __forceinline__ void cp_async16(u32 dst, const void* src) {
    asm volatile("cp.async.cg.shared.global [%0],[%1],16;" :: "r"(dst), "l"(src));
}

// ---------------------------------------------------------------------------
// Prep (once): W -> fp16, stored pre-swizzled:
//   short-off(n, k) = n*256 + (((k>>3) ^ (n&7)) << 3) + (k&7)
// ---------------------------------------------------------------------------
__global__ void prep_w_kernel(const float* __restrict__ W,
                              const float* __restrict__ bias)
{
    int gid = blockIdx.x * 256 + threadIdx.x;   // 48*256 = 12288 threads
    int n = gid >> 8, k = gid & 255;
    unsigned short hi = 0;
    if (n < OUTC) {
        float w = __ldg(W + k * OUTC + n);
        __half h = __float2half_rn(w);
        hi = *(const unsigned short*)&h;
    }
    int off = n * 256 + (((k >> 3) ^ (n & 7)) << 3) + (k & 7);
    g_Bhi[off] = hi;
    if (gid < 48) g_bias48[gid] = (gid < OUTC) ? __ldg(bias + gid) : 0.0f;
}

// ---------------------------------------------------------------------------
__global__ __launch_bounds__(TPB, 2)
void fused_kernel(const float* __restrict__ x, const float* __restrict__ state,
                  float* __restrict__ out)
{
    extern __shared__ __align__(1024) char sm[];
    const u32 smb = sm2u32(sm);
    const int tid = threadIdx.x;
    const int wid = tid >> 5;
    const int lane = tid & 31;

    // ---- B tile via cp.async (pre-swizzled layout: straight 16B copy) ----
    {
        const uint4* sh = (const uint4*)g_Bhi;   // 1536 uint4
        #pragma unroll
        for (int j = 0; j < 6; j++) {
            int i = tid + j * TPB;
            cp_async16(smb + B_HI + 16 * i, sh + i);
        }
        asm volatile("cp.async.commit_group;");
    }

    // ---- x -> fp16 into swizzled A tile ----
    const float4* xsrc = (const float4*)(x + (size_t)blockIdx.x * RPB * KDIM);
    #pragma unroll 4
    for (int j = 0; j < (RPB * KDIM / 4) / TPB; j++) {      // 32 iters
        int idx = tid + j * TPB;
        int r = idx >> 6, k4 = idx & 63;                     // k4: float4 idx in row
        float4 v = __ldg(xsrc + idx);
        __half2 h01 = __floats2half2_rn(v.x, v.y);           // .x = low half
        __half2 h23 = __floats2half2_rn(v.z, v.w);
        u32 off = (u32)(r * 512) + ((((u32)k4 >> 1) ^ ((u32)r & 7u)) << 4)
                + ((u32)k4 & 1u) * 8u;
        *(uint2*)(sm + A_HI + off) =
            make_uint2(*(const u32*)&h01, *(const u32*)&h23);
    }
    asm volatile("cp.async.wait_group 0;");
    __syncthreads();

    // ---- MMA: 8 warps = 4 m-tiles(32 rows) x 2 k-halves; single pass ----
    const int mw = wid & 3;            // m-tile: rows mw*32..+31
    const int kh = wid >> 2;           // k-half: k16 steps kh*8..+7

    float c[2][6][4];
    #pragma unroll
    for (int s2 = 0; s2 < 2; s2++)
        #pragma unroll
        for (int n = 0; n < 6; n++)
            #pragma unroll
            for (int q = 0; q < 4; q++) c[s2][n][q] = 0.0f;

    const u32 sw  = (u32)(lane & 7);                 // per-thread swizzle constant
    const u32 arow = (u32)((mw * 32 + (lane & 15)) * 512);
    const u32 acolL = (u32)(lane >> 4);              // 0/1: +8 k within step
    const u32 brow = (u32)((((lane & 7) | ((lane >> 4) << 3))) * 512);
    const u32 bcolL = (u32)((lane >> 3) & 1);

    #pragma unroll
    for (int s = 0; s < 8; s++) {
        u32 step = (u32)(kh * 8 + s);                // k16 step 0..15
        u32 ac = ((step * 2u + acolL) ^ sw) << 4;    // A 16B col, swizzled
        u32 bc = ((step * 2u + bcolL) ^ sw) << 4;    // B 16B col, swizzled
        u32 ah[2][4], bh[12];
        #pragma unroll
        for (int sub = 0; sub < 2; sub++) {
            u32 ad = arow + (u32)sub * (16u * 512u) + ac;
            ldsm4(smb + A_HI + ad, ah[sub][0], ah[sub][1], ah[sub][2], ah[sub][3]);
        }
        #pragma unroll
        for (int nt = 0; nt < 3; nt++) {
            u32 bd = brow + (u32)nt * (16u * 512u) + bc;
            ldsm4(smb + B_HI + bd, bh[nt*4], bh[nt*4+1], bh[nt*4+2], bh[nt*4+3]);
        }
        #pragma unroll
        for (int sub = 0; sub < 2; sub++)
            #pragma unroll
            for (int n = 0; n < 6; n++) {
                int bi = (n >> 1) * 4 + (n & 1) * 2;
                mma16816(c[sub][n], ah[sub], bh[bi], bh[bi + 1]);
            }
    }
    __syncthreads();   // tile reads done before aliases are written

    // ---- stage C partials: cs[kh][row][col], row stride 50 floats ----
    {
        float* cs = (float*)(sm + CS) + kh * (RPB * 50);
        int c0 = 2 * (lane & 3);
        #pragma unroll
        for (int sub = 0; sub < 2; sub++) {
            int r0 = mw * 32 + sub * 16 + (lane >> 2);
            #pragma unroll
            for (int n = 0; n < 6; n++) {
                int col = n * 8 + c0;
                *(float2*)&cs[r0 * 50 + col]       = make_float2(c[sub][n][0], c[sub][n][1]);
                *(float2*)&cs[(r0 + 8) * 50 + col] = make_float2(c[sub][n][2], c[sub][n][3]);
            }
        }
    }
    __syncthreads();

    // ---- epilogue: linear DMP map, 2 threads per row (t-split) ----
    {
        const int row  = tid & 127;
        const int half = tid >> 7;                   // 0: t 0..5, 1: t 6..10
        const float* cs = (const float*)(sm + CS) + row * 50;
        float* eb = (float*)(sm + EB) + row * 77;
        const float* st = state + ((size_t)(blockIdx.x * RPB + row)) * DOF;

        float g[DOF], y0v[DOF], ku[DOF], wv[DOF][NB];
        #pragma unroll
        for (int d = 0; d < DOF; d++) {
            y0v[d] = __ldg(st + d);
            g[d] = cs[d] + cs[RPB*50 + d] + __ldg(g_bias48 + d);
            ku[d] = g[d] - y0v[d];
            #pragma unroll
            for (int j = 0; j < NB; j++) {
                int col = DOF + 5 * d + j;
                wv[d][j] = cs[col] + cs[RPB*50 + col] + __ldg(g_bias48 + col);
            }
            if (half == 0) eb[d] = y0v[d];           // t = 0
        }
        int t0 = half ? 6 : 1, t1 = half ? 10 : 5;
        for (int t = t0; t <= t1; t++) {
            float a0 = c_A[t*8+0], a1 = c_A[t*8+1], a2 = c_A[t*8+2], a3 = c_A[t*8+3];
            float a4 = c_A[t*8+4], a5 = c_A[t*8+5], a6 = c_A[t*8+6], a7 = c_A[t*8+7];
            #pragma unroll
            for (int d = 0; d < DOF; d++) {
                float v = a2 * wv[d][0];
                v = fmaf(a3, wv[d][1], v);
                v = fmaf(a4, wv[d][2], v);
                v = fmaf(a5, wv[d][3], v);
                v = fmaf(a6, wv[d][4], v);
                float yv = fmaf(a0, y0v[d], a7);
                yv = fmaf(a1, g[d], yv);
                yv = fmaf(v, ku[d], yv);
                eb[t * 7 + d] = yv;
            }
        }
    }
    __syncthreads();

    // ---- coalesced output copy: 128*77 floats = 2464 float4 ----
    const float4* s4 = (const float4*)(sm + EB);
    float4* d4 = (float4*)(out + (size_t)blockIdx.x * RPB * 77);
    #pragma unroll
    for (int j = 0; j < 10; j++) {
        int i = tid + j * TPB;
        if (i < (RPB * 77) / 4) d4[i] = s4[i];
    }
}

// ---------------------------------------------------------------------------
// Host: DMP linear map A (8 basis runs of the exact fp32 recursion).
// ---------------------------------------------------------------------------
static float hA[11 * 8];

static void compute_A_host() {
    float c[NB], s2[NB], P[100][NB];
    const float n15 = 11.180339887498949f;     // 5^1.5
    for (int j = 0; j < NB; j++) { c[j] = expf(-0.25f * j); s2[j] = n15 / c[j]; }
    float xv = 1.0f;
    for (int s = 0; s < 100; s++) {
        xv = xv - xv * 0.01f;
        float sum = 0.0f, psi[NB];
        for (int j = 0; j < NB; j++) {
            float d = xv - c[j];
            psi[j] = expf(-0.5f * d * d / s2[j]);
            sum += psi[j];
        }
        for (int j = 0; j < NB; j++) P[s][j] = psi[j] * xv / sum;
    }
    for (int b = 0; b < 8; b++) {              // basis: y0, g, u0..u4, const
        float y = (b == 0) ? 1.0f : 0.0f;
        float gb = (b == 1) ? 1.0f : 0.0f;
        float u[NB];
        for (int j = 0; j < NB; j++) u[j] = (b == 2 + j) ? 1.0f : 0.0f;
        float z = (b == 7) ? 0.05f : 0.0f;
        hA[0 * 8 + b] = y;
        int s = 0;
        for (int tt = 1; tt <= 10; tt++) {
            for (int ss = 0; ss < 10; ss++, s++) {
                float fx = 0.0f;
                for (int j = 0; j < NB; j++) fx += P[s][j] * u[j];
                float dz = 56.25f * (gb - y) - 15.0f * z + fx;
                y = y + z * 0.01f;             // uses old z
                z = z + dz * 0.01f;
            }
            hA[tt * 8 + b] = y;
        }
    }
}

extern "C" void kernel_launch(void* const* d_in, const int* in_sizes, int n_in,
                              void* d_out, int out_size)
{
    const float* x     = (const float*)d_in[0];
    const float* state = (const float*)d_in[1];
    const float* W     = (const float*)d_in[2];
    const float* b     = (const float*)d_in[3];
    float* out = (float*)d_out;

    compute_A_host();
    cudaMemcpyToSymbolAsync(c_A, hA, sizeof(hA), 0, cudaMemcpyHostToDevice);

    prep_w_kernel<<<48, 256>>>(W, b);
    cudaFuncSetAttribute(fused_kernel,
                         cudaFuncAttributeMaxDynamicSharedMemorySize, SMEM_TOTAL);
    fused_kernel<<<GRID, TPB, SMEM_TOTAL>>>(x, state, out);
}

// round 13
// speedup vs baseline: 1.8739x; 1.0819x over previous
#include <cuda_runtime.h>
#include <cuda_fp16.h>
#include <math.h>

typedef unsigned int u32;

#define DOF   7
#define NB    5
#define KDIM  256
#define OUTC  42
#define RPB   64
#define BATCH 65536
#define GRID  (BATCH / RPB)   // 1024
#define TPB   256

// ---- smem layout (bytes). Unpadded 512B rows, XOR-swizzled:
// phys16(r, c) = (c ^ (r & 7)), 16B units; conflict-free for STS/LDSM/cp.async.
#define A_HI   0                    // 64 x 512 = 32768 (x in fp16)
#define B_HI   32768                // 48 x 512 = 24576 -> 57344 (W fp16, single)
#define SMEM_TOTAL 57600            // x3 CTAs = 172800 < SM limit
// aliases after MMA:
#define CS     0                    // 2 x (64*50*4) = 25600 (over A tile)
#define EB     25600                // 64*77*4 = 19712 -> 45312 < 57344

// Pre-converted, PRE-SWIZZLED W tile (exact smem byte layout, 48x512B)
__device__ __align__(16) unsigned short g_Bhi[48 * 256];
__device__ __align__(16) float g_bias48[48];

// DMP linear map: y[t] = A[t] . [y0, g, u0..u4, 1]
__constant__ float c_A[11 * 8];

__device__ __forceinline__ u32 sm2u32(const void* p) {
    u32 a; asm("{.reg .u64 t; cvta.to.shared.u64 t,%1; cvt.u32.u64 %0,t;}"
               : "=r"(a) : "l"(p));
    return a;
}
__device__ __forceinline__ void ldsm4(u32 addr, u32& r0, u32& r1, u32& r2, u32& r3) {
    asm volatile("ldmatrix.sync.aligned.m8n8.x4.shared.b16 {%0,%1,%2,%3},[%4];"
                 : "=r"(r0), "=r"(r1), "=r"(r2), "=r"(r3) : "r"(addr));
}
__device__ __forceinline__ void mma16816(float* c, const u32* a, u32 b0, u32 b1) {
    asm volatile(
        "mma.sync.aligned.m16n8k16.row.col.f32.f16.f16.f32 "
        "{%0,%1,%2,%3},{%4,%5,%6,%7},{%8,%9},{%0,%1,%2,%3};"
        : "+f"(c[0]), "+f"(c[1]), "+f"(c[2]), "+f"(c[3])
        : "r"(a[0]), "r"(a[1]), "r"(a[2]), "r"(a[3]), "r"(b0), "r"(b1));
}
__device__ __forceinline__ void cp_async16(u32 dst, const void* src) {
    asm volatile("cp.async.cg.shared.global [%0],[%1],16;" :: "r"(dst), "l"(src));
}

// ---------------------------------------------------------------------------
// Prep (once): W -> fp16, stored pre-swizzled:
//   short-off(n, k) = n*256 + (((k>>3) ^ (n&7)) << 3) + (k&7)
// ---------------------------------------------------------------------------
__global__ void prep_w_kernel(const float* __restrict__ W,
                              const float* __restrict__ bias)
{
    int gid = blockIdx.x * 256 + threadIdx.x;   // 48*256 = 12288 threads
    int n = gid >> 8, k = gid & 255;
    unsigned short hi = 0;
    if (n < OUTC) {
        float w = __ldg(W + k * OUTC + n);
        __half h = __float2half_rn(w);
        hi = *(const unsigned short*)&h;
    }
    int off = n * 256 + (((k >> 3) ^ (n & 7)) << 3) + (k & 7);
    g_Bhi[off] = hi;
    if (gid < 48) g_bias48[gid] = (gid < OUTC) ? __ldg(bias + gid) : 0.0f;
}

// ---------------------------------------------------------------------------
__global__ __launch_bounds__(TPB, 3)
void fused_kernel(const float* __restrict__ x, const float* __restrict__ state,
                  float* __restrict__ out)
{
    extern __shared__ __align__(1024) char sm[];
    const u32 smb = sm2u32(sm);
    const int tid = threadIdx.x;
    const int wid = tid >> 5;
    const int lane = tid & 31;

    // ---- B tile via cp.async (pre-swizzled layout: straight 16B copy) ----
    {
        const uint4* sh = (const uint4*)g_Bhi;   // 1536 uint4
        #pragma unroll
        for (int j = 0; j < 6; j++) {
            int i = tid + j * TPB;
            cp_async16(smb + B_HI + 16 * i, sh + i);
        }
        asm volatile("cp.async.commit_group;");
    }

    // ---- x -> fp16 into swizzled A tile; batched loads for high MLP ----
    const float4* xsrc = (const float4*)(x + (size_t)blockIdx.x * RPB * KDIM);
    #pragma unroll
    for (int h = 0; h < 2; h++) {
        float4 v[8];
        #pragma unroll
        for (int j = 0; j < 8; j++)
            v[j] = __ldg(xsrc + tid + (h * 8 + j) * TPB);
        #pragma unroll
        for (int j = 0; j < 8; j++) {
            int idx = tid + (h * 8 + j) * TPB;
            int r = idx >> 6, k4 = idx & 63;
            __half2 h01 = __floats2half2_rn(v[j].x, v[j].y);
            __half2 h23 = __floats2half2_rn(v[j].z, v[j].w);
            u32 off = (u32)(r * 512) + ((((u32)k4 >> 1) ^ ((u32)r & 7u)) << 4)
                    + ((u32)k4 & 1u) * 8u;
            *(uint2*)(sm + A_HI + off) =
                make_uint2(*(const u32*)&h01, *(const u32*)&h23);
        }
    }
    asm volatile("cp.async.wait_group 0;");
    __syncthreads();

    // ---- MMA: 8 warps = 4 m-tiles(16 rows) x 2 k-halves; single pass ----
    const int mw = wid & 3;            // m-tile: rows mw*16..+15
    const int kh = wid >> 2;           // k-half: k16 steps kh*8..+7

    float c[6][4];
    #pragma unroll
    for (int n = 0; n < 6; n++)
        #pragma unroll
        for (int q = 0; q < 4; q++) c[n][q] = 0.0f;

    const u32 sw  = (u32)(lane & 7);                 // per-thread swizzle constant
    const u32 arow = (u32)((mw * 16 + (lane & 15)) * 512);
    const u32 acolL = (u32)(lane >> 4);              // 0/1: +8 k within step
    const u32 brow = (u32)((((lane & 7) | ((lane >> 4) << 3))) * 512);
    const u32 bcolL = (u32)((lane >> 3) & 1);

    #pragma unroll
    for (int s = 0; s < 8; s++) {
        u32 step = (u32)(kh * 8 + s);                // k16 step 0..15
        u32 ac = ((step * 2u + acolL) ^ sw) << 4;    // A 16B col, swizzled
        u32 bc = ((step * 2u + bcolL) ^ sw) << 4;    // B 16B col, swizzled
        u32 ah[4], bh[12];
        ldsm4(smb + A_HI + arow + ac, ah[0], ah[1], ah[2], ah[3]);
        #pragma unroll
        for (int nt = 0; nt < 3; nt++) {
            u32 bd = brow + (u32)nt * (16u * 512u) + bc;
            ldsm4(smb + B_HI + bd, bh[nt*4], bh[nt*4+1], bh[nt*4+2], bh[nt*4+3]);
        }
        #pragma unroll
        for (int n = 0; n < 6; n++) {
            int bi = (n >> 1) * 4 + (n & 1) * 2;
            mma16816(c[n], ah, bh[bi], bh[bi + 1]);
        }
    }
    __syncthreads();   // tile reads done before aliases are written

    // ---- stage C partials: cs[kh][row][col], row stride 50 floats ----
    {
        float* cs = (float*)(sm + CS) + kh * (RPB * 50);
        int c0 = 2 * (lane & 3);
        int r0 = mw * 16 + (lane >> 2);
        #pragma unroll
        for (int n = 0; n < 6; n++) {
            int col = n * 8 + c0;
            *(float2*)&cs[r0 * 50 + col]       = make_float2(c[n][0], c[n][1]);
            *(float2*)&cs[(r0 + 8) * 50 + col] = make_float2(c[n][2], c[n][3]);
        }
    }
    __syncthreads();

    // ---- epilogue: linear DMP map, 2 threads per row (t-split) ----
    if (tid < 2 * RPB) {
        const int row  = tid & 63;
        const int half = tid >> 6;                   // 0: t 0..5, 1: t 6..10
        const float* cs = (const float*)(sm + CS) + row * 50;
        float* eb = (float*)(sm + EB) + row * 77;
        const float* st = state + ((size_t)(blockIdx.x * RPB + row)) * DOF;

        float g[DOF], y0v[DOF], ku[DOF], wv[DOF][NB];
        #pragma unroll
        for (int d = 0; d < DOF; d++) y0v[d] = __ldg(st + d);
        #pragma unroll
        for (int d = 0; d < DOF; d++) {
            g[d] = cs[d] + cs[RPB*50 + d] + __ldg(g_bias48 + d);
            ku[d] = g[d] - y0v[d];
            #pragma unroll
            for (int j = 0; j < NB; j++) {
                int col = DOF + 5 * d + j;
                wv[d][j] = cs[col] + cs[RPB*50 + col] + __ldg(g_bias48 + col);
            }
            if (half == 0) eb[d] = y0v[d];           // t = 0
        }
        int t0 = half ? 6 : 1, t1 = half ? 10 : 5;
        for (int t = t0; t <= t1; t++) {
            float a0 = c_A[t*8+0], a1 = c_A[t*8+1], a2 = c_A[t*8+2], a3 = c_A[t*8+3];
            float a4 = c_A[t*8+4], a5 = c_A[t*8+5], a6 = c_A[t*8+6], a7 = c_A[t*8+7];
            #pragma unroll
            for (int d = 0; d < DOF; d++) {
                float v = a2 * wv[d][0];
                v = fmaf(a3, wv[d][1], v);
                v = fmaf(a4, wv[d][2], v);
                v = fmaf(a5, wv[d][3], v);
                v = fmaf(a6, wv[d][4], v);
                float yv = fmaf(a0, y0v[d], a7);
                yv = fmaf(a1, g[d], yv);
                yv = fmaf(v, ku[d], yv);
                eb[t * 7 + d] = yv;
            }
        }
    }
    __syncthreads();

    // ---- coalesced output copy: 64*77 floats = 1232 float4 ----
    const float4* s4 = (const float4*)(sm + EB);
    float4* d4 = (float4*)(out + (size_t)blockIdx.x * RPB * 77);
    #pragma unroll
    for (int j = 0; j < 5; j++) {
        int i = tid + j * TPB;
        if (i < (RPB * 77) / 4) d4[i] = s4[i];
    }
}

// ---------------------------------------------------------------------------
// Host: DMP linear map A (8 basis runs of the exact fp32 recursion).
// ---------------------------------------------------------------------------
static float hA[11 * 8];

static void compute_A_host() {
    float c[NB], s2[NB], P[100][NB];
    const float n15 = 11.180339887498949f;     // 5^1.5
    for (int j = 0; j < NB; j++) { c[j] = expf(-0.25f * j); s2[j] = n15 / c[j]; }
    float xv = 1.0f;
    for (int s = 0; s < 100; s++) {
        xv = xv - xv * 0.01f;
        float sum = 0.0f, psi[NB];
        for (int j = 0; j < NB; j++) {
            float d = xv - c[j];
            psi[j] = expf(-0.5f * d * d / s2[j]);
            sum += psi[j];
        }
        for (int j = 0; j < NB; j++) P[s][j] = psi[j] * xv / sum;
    }
    for (int b = 0; b < 8; b++) {              // basis: y0, g, u0..u4, const
        float y = (b == 0) ? 1.0f : 0.0f;
        float gb = (b == 1) ? 1.0f : 0.0f;
        float u[NB];
        for (int j = 0; j < NB; j++) u[j] = (b == 2 + j) ? 1.0f : 0.0f;
        float z = (b == 7) ? 0.05f : 0.0f;
        hA[0 * 8 + b] = y;
        int s = 0;
        for (int tt = 1; tt <= 10; tt++) {
            for (int ss = 0; ss < 10; ss++, s++) {
                float fx = 0.0f;
                for (int j = 0; j < NB; j++) fx += P[s][j] * u[j];
                float dz = 56.25f * (gb - y) - 15.0f * z + fx;
                y = y + z * 0.01f;             // uses old z
                z = z + dz * 0.01f;
            }
            hA[tt * 8 + b] = y;
        }
    }
}

extern "C" void kernel_launch(void* const* d_in, const int* in_sizes, int n_in,
                              void* d_out, int out_size)
{
    const float* x     = (const float*)d_in[0];
    const float* state = (const float*)d_in[1];
    const float* W     = (const float*)d_in[2];
    const float* b     = (const float*)d_in[3];
    float* out = (float*)d_out;

    compute_A_host();
    cudaMemcpyToSymbolAsync(c_A, hA, sizeof(hA), 0, cudaMemcpyHostToDevice);

    prep_w_kernel<<<48, 256>>>(W, b);
    cudaFuncSetAttribute(fused_kernel,
                         cudaFuncAttributeMaxDynamicSharedMemorySize, SMEM_TOTAL);
    fused_kernel<<<GRID, TPB, SMEM_TOTAL>>>(x, state, out);
}